// round 12
// baseline (speedup 1.0000x reference)
#include <cuda_runtime.h>
#include <cuda_bf16.h>
#include <mma.h>
#include <cstdint>

using namespace nvcuda;

#define BB   256
#define LL   512
#define FF   64
#define LF   32768
#define NTOT 8388608
#define HH   128
#define H2   256
#define ND   64

// ---------------- device globals ----------------
__device__ __align__(16) uint32_t g_h3b[BB * (H2 / 2)];   // h3 bf16: [256 rows][256]
__device__ float  g_scale[BB * FF];
__device__ float  g_freq[NTOT];

// ---------------- threefry2x32 (JAX) ----------------
__device__ __forceinline__ uint2 tf2x32(uint32_t k0, uint32_t k1, uint32_t x0, uint32_t x1) {
    uint32_t k2 = k0 ^ k1 ^ 0x1BD11BDAu;
    x0 += k0; x1 += k1;
#define TFR(r) { x0 += x1; x1 = (x1 << (r)) | (x1 >> (32 - (r))); x1 ^= x0; }
    TFR(13) TFR(15) TFR(26) TFR(6)
    x0 += k1; x1 += k2 + 1u;
    TFR(17) TFR(29) TFR(16) TFR(24)
    x0 += k2; x1 += k0 + 2u;
    TFR(13) TFR(15) TFR(26) TFR(6)
    x0 += k0; x1 += k1 + 3u;
    TFR(17) TFR(29) TFR(16) TFR(24)
    x0 += k1; x1 += k2 + 4u;
    TFR(13) TFR(15) TFR(26) TFR(6)
    x0 += k2; x1 += k0 + 5u;
#undef TFR
    return make_uint2(x0, x1);
}
__device__ __forceinline__ uint32_t tf_bits(uint2 key, uint32_t e) {
    uint2 r = tf2x32(key.x, key.y, 0u, e);
    return r.x ^ r.y;
}
__device__ __forceinline__ float u01_from_bits(uint32_t bits) {
    return __uint_as_float((bits >> 9) | 0x3f800000u) - 1.0f;
}
__device__ __forceinline__ float tf_normal(uint2 key, uint32_t e) {
    float u = u01_from_bits(tf_bits(key, e));
    const float lo = -0.99999994f;
    float v = u * 2.0f + lo;
    v = fmaxf(lo, v);
    return 1.4142135623730951f * erfinvf(v);
}
// exact versions (used on scalar/setup paths)
__device__ __forceinline__ float sigmf(float x)  { return 1.0f / (1.0f + expf(-x)); }
__device__ __forceinline__ float softplusf(float x) { return fmaxf(x, 0.0f) + log1pf(expf(-fabsf(x))); }
// fast versions (bulk paths; abs err ~4e-7, output sensitivity <= 0.0125)
__device__ __forceinline__ float sigmf_fast(float x)  { return __fdividef(1.0f, 1.0f + __expf(-x)); }
__device__ __forceinline__ float softplusf_fast(float x) { return fmaxf(x, 0.0f) + __logf(1.0f + __expf(-fabsf(x))); }

__device__ __forceinline__ float2 cadd(float2 a, float2 b) { return make_float2(a.x + b.x, a.y + b.y); }
__device__ __forceinline__ float2 csub(float2 a, float2 b) { return make_float2(a.x - b.x, a.y - b.y); }
__device__ __forceinline__ float2 cmul(float2 a, float2 w) { return make_float2(a.x * w.x - a.y * w.y, a.x * w.y + a.y * w.x); }
__device__ __forceinline__ float2 cmulc(float2 w, float2 b) { return make_float2(w.x * b.x + w.y * b.y, w.x * b.y - w.y * b.x); }

// ---------------- kernel 1: FFT-aug (blocks 0..2047) + MLP (2048..2303) -----
__global__ __launch_bounds__(256) void fft_mlp(
    const float* __restrict__ x,
    const float* __restrict__ w1, const float* __restrict__ b1,
    const float* __restrict__ w2, const float* __restrict__ b2,
    const float* __restrict__ w3, const float* __restrict__ b3,
    const float* __restrict__ ws, const float* __restrict__ bs,
    const float* __restrict__ psh, const float* __restrict__ psc)
{
    __shared__ float2 s[512][9];
    __shared__ float2 tw[256];
    __shared__ float zb[ND], h1b[HH], h2b[H2], h3b[H2];
    int tid = threadIdx.x;

    if (blockIdx.x >= 2048) {
        // ------- MLP path -------
        int m = blockIdx.x - 2048, t = tid;
        uint2 kz = tf2x32(0u, 42u, 0u, 0u);
        if (t < ND) zb[t] = tf_normal(kz, (uint32_t)(m * ND + t));
        __syncthreads();
        if (t < HH) {
            float acc = b1[t];
#pragma unroll 8
            for (int k = 0; k < ND; k++) acc = fmaf(zb[k], w1[k * HH + t], acc);
            h1b[t] = acc > 0.0f ? acc : 0.2f * acc;
        }
        __syncthreads();
        {
            float acc = b2[t];
#pragma unroll 8
            for (int k = 0; k < HH; k++) acc = fmaf(h1b[k], w2[k * H2 + t], acc);
            h2b[t] = acc > 0.0f ? acc : 0.2f * acc;
        }
        __syncthreads();
        {
            float acc = b3[t];
#pragma unroll 8
            for (int k = 0; k < H2; k++) acc = fmaf(h2b[k], w3[k * H2 + t], acc);
            h3b[t] = acc > 0.0f ? acc : 0.2f * acc;
        }
        __syncthreads();
        if (t < H2 / 2) {
            __nv_bfloat162 p = __floats2bfloat162_rn(h3b[2 * t], h3b[2 * t + 1]);
            g_h3b[m * (H2 / 2) + t] = *reinterpret_cast<uint32_t*>(&p);
        }
        if (t < FF) {
            float s_scale = sigmf(*psc);
            float acc = bs[t];
#pragma unroll 8
            for (int k = 0; k < H2; k++) acc = fmaf(h3b[k], ws[k * FF + t], acc);
            g_scale[m * FF + t] = 1.0f + (softplusf(acc) - 0.5f) * 0.2f * s_scale;
        }
        return;
    }

    // ------- FFT path: 8 f-columns per block, DIF fwd -> mask -> DIT inv -------
    float ss_ = sigmf(*psh);
    float smix = 1.0f - ss_;
    float ratio = fminf(smix * 0.1f, 0.5f);
    uint2 kf = tf2x32(0u, 42u, 0u, 4u);

    int bidx = blockIdx.x;
    int b = bidx >> 3;
    int f0 = (bidx & 7) * 8;
    const float* xp = x + (size_t)b * LF + f0;
    {
        float sv, cv;
        sincosf(-6.283185307179586f * (float)tid / 512.0f, &sv, &cv);
        tw[tid] = make_float2(cv, sv);
    }
#pragma unroll
    for (int it = 0; it < 16; it++) {
        int u = it * 256 + tid;
        int ff = u & 7, l = u >> 3;
        s[l][ff] = make_float2(xp[(size_t)l * FF + ff], 0.0f);
    }
    __syncthreads();
    // forward DIF, stages fused in pairs (0,1),(2,3),(4,5),(6,7)
#pragma unroll
    for (int st = 0; st < 8; st += 2) {
        const int half  = 256 >> st;
        const int half2 = 128 >> st;
#pragma unroll
        for (int it = 0; it < 4; it++) {
            int u = it * 256 + tid;
            int ff = u & 7, gi = u >> 3;
            int k2 = gi & (half2 - 1);
            int g  = gi >> (7 - st);
            int p0 = (g << (9 - st)) + k2;
            float2 a0 = s[p0][ff], a1 = s[p0 + half2][ff];
            float2 a2 = s[p0 + half][ff], a3 = s[p0 + half + half2][ff];
            float2 w02 = tw[k2 << st];
            float2 w13 = tw[(k2 + half2) << st];
            float2 wnx = tw[k2 << (st + 1)];
            float2 A0 = cadd(a0, a2);
            float2 A2 = cmul(csub(a0, a2), w02);
            float2 A1 = cadd(a1, a3);
            float2 A3 = cmul(csub(a1, a3), w13);
            s[p0][ff]                 = cadd(A0, A1);
            s[p0 + half2][ff]         = cmul(csub(A0, A1), wnx);
            s[p0 + half][ff]          = cadd(A2, A3);
            s[p0 + half + half2][ff]  = cmul(csub(A2, A3), wnx);
        }
        __syncthreads();
    }
    // fused: fwd final radix-2 (st=8) + keep-mask + inv radix-2 (st=0), in registers
#pragma unroll
    for (int it = 0; it < 8; it++) {
        int u = it * 256 + tid;
        int ff = u & 7, bi = u >> 3;
        int p = bi << 1;
        float2 a = s[p][ff], bv = s[p + 1][ff];
        float2 X0 = cadd(a, bv);                 // spectrum at j0 = brev9(p)
        float2 X1 = csub(a, bv);                 // spectrum at j1 = brev9(p+1)
        int j0 = (int)(__brev((unsigned)p) >> 23);
        int j1 = (int)(__brev((unsigned)(p + 1)) >> 23);
        uint32_t e0 = (uint32_t)b * LF + (uint32_t)j0 * FF + (uint32_t)(f0 + ff);
        uint32_t e1 = (uint32_t)b * LF + (uint32_t)j1 * FF + (uint32_t)(f0 + ff);
        if (!(u01_from_bits(tf_bits(kf, e0)) > ratio)) X0 = make_float2(0.0f, 0.0f);
        if (!(u01_from_bits(tf_bits(kf, e1)) > ratio)) X1 = make_float2(0.0f, 0.0f);
        s[p][ff]     = cadd(X0, X1);
        s[p + 1][ff] = csub(X0, X1);
    }
    __syncthreads();
    // inverse DIT fused pairs (1,2),(3,4),(5,6),(7,8)
#pragma unroll
    for (int st = 1; st < 9; st += 2) {
        const int half = 1 << st;
#pragma unroll
        for (int it = 0; it < 4; it++) {
            int u = it * 256 + tid;
            int ff = u & 7, gi = u >> 3;
            int k = gi & (half - 1);
            int g = gi >> st;
            int p0 = (g << (st + 2)) + k;
            float2 a0 = s[p0][ff], a1 = s[p0 + half][ff];
            float2 a2 = s[p0 + 2 * half][ff], a3 = s[p0 + 3 * half][ff];
            float2 wa_ = tw[k << (8 - st)];
            float2 wb_ = tw[k << (7 - st)];
            float2 wc_ = tw[(k + half) << (7 - st)];
            float2 t01 = cmulc(wa_, a1);
            float2 t23 = cmulc(wa_, a3);
            float2 A0 = cadd(a0, t01), A1 = csub(a0, t01);
            float2 A2 = cadd(a2, t23), A3 = csub(a2, t23);
            float2 tB = cmulc(wb_, A2), tC = cmulc(wc_, A3);
            s[p0][ff]             = cadd(A0, tB);
            s[p0 + 2 * half][ff]  = csub(A0, tB);
            s[p0 + half][ff]      = cadd(A1, tC);
            s[p0 + 3 * half][ff]  = csub(A1, tC);
        }
        __syncthreads();
    }
#pragma unroll
    for (int it = 0; it < 16; it++) {
        int u = it * 256 + tid;
        int ff = u & 7, l = u >> 3;
        float val = s[l][ff].x * (1.0f / 512.0f);
        if (smix < 0.01f) val = xp[(size_t)l * FF + ff];
        g_freq[(size_t)b * LF + (size_t)l * FF + f0 + ff] = val;
    }
}

// ---------------- kernel 2: wmma bf16 dual GEMM (M=256) + fused epilogue ----
#define BPLD 72
#define STG  68
#define SM_PAN_N 36864
#define SM_ST    73728
#define DYN_SMEM (73728 + 2 * 256 * STG * 4)   // 212992 B

__global__ __launch_bounds__(512) void final_mma(
    const float* __restrict__ x,
    const float* __restrict__ wm, const float* __restrict__ bmv,
    const float* __restrict__ wn, const float* __restrict__ bnv,
    float* __restrict__ out,
    const float* __restrict__ pm, const float* __restrict__ pn,
    const float* __restrict__ psh)
{
    extern __shared__ char smem[];
    __nv_bfloat16* Bm = reinterpret_cast<__nv_bfloat16*>(smem);
    __nv_bfloat16* Bn = reinterpret_cast<__nv_bfloat16*>(smem + SM_PAN_N);
    float* stage = reinterpret_cast<float*>(smem + SM_ST);
    __shared__ int swp[256], ssh[256];
    __shared__ float sbm[64], sbn[64];
    int tid = threadIdx.x;
    int wid = tid >> 5;
    int n0 = blockIdx.x * 64;
    int l_idx = blockIdx.x;
    const __nv_bfloat16* Ag = reinterpret_cast<const __nv_bfloat16*>(g_h3b);

    // ---- per-CTA wp/sh randint ----
    if (tid < 256) {
        float ss_ = sigmf(*psh);
        int ws_ = (int)(51.2f * ss_);
        uint2 kwp = tf2x32(0u, 42u, 0u, 2u);
        uint2 ksh = tf2x32(0u, 42u, 0u, 3u);
        uint2 skwp1 = tf2x32(kwp.x, kwp.y, 0u, 0u);
        uint2 skwp2 = tf2x32(kwp.x, kwp.y, 0u, 1u);
        uint2 sksh1 = tf2x32(ksh.x, ksh.y, 0u, 0u);
        uint2 sksh2 = tf2x32(ksh.x, ksh.y, 0u, 1u);
        {
            uint32_t span = (uint32_t)max(1, (512 - ws_) - ws_);
            uint32_t mult = 65536u % span; mult = (mult * mult) % span;
            uint32_t hi = tf_bits(skwp1, (uint32_t)tid);
            uint32_t lo = tf_bits(skwp2, (uint32_t)tid);
            uint32_t off = ((hi % span) * mult + (lo % span)) % span;
            swp[tid] = ws_ + (int)off;
        }
        {
            uint32_t span = (uint32_t)(2 * ws_ + 1); if (span == 0u) span = 1u;
            uint32_t mult = 65536u % span; mult = (mult * mult) % span;
            uint32_t hi = tf_bits(sksh1, (uint32_t)tid);
            uint32_t lo = tf_bits(sksh2, (uint32_t)tid);
            uint32_t off = ((hi % span) * mult + (lo % span)) % span;
            ssh[tid] = -ws_ + (int)off;
        }
    }
    if (tid >= 256 && tid < 320) { sbm[tid - 256] = bmv[n0 + tid - 256]; }
    if (tid >= 320 && tid < 384) { sbn[tid - 320] = bnv[n0 + tid - 320]; }

    // ---- preload BOTH panels: K=256 x N=64 fp32 -> bf16 smem, loaded once ----
#pragma unroll
    for (int i = 0; i < 4; i++) {
        int u = i * 512 + tid;
        int r = u >> 3, c = (u & 7) * 8;
        {
            const float4* src = reinterpret_cast<const float4*>(wm + (size_t)r * LF + n0 + c);
            float4 v0 = src[0], v1 = src[1];
            __nv_bfloat162 p0 = __floats2bfloat162_rn(v0.x, v0.y);
            __nv_bfloat162 p1 = __floats2bfloat162_rn(v0.z, v0.w);
            __nv_bfloat162 p2 = __floats2bfloat162_rn(v1.x, v1.y);
            __nv_bfloat162 p3 = __floats2bfloat162_rn(v1.z, v1.w);
            uint4 pk = make_uint4(*reinterpret_cast<uint32_t*>(&p0), *reinterpret_cast<uint32_t*>(&p1),
                                  *reinterpret_cast<uint32_t*>(&p2), *reinterpret_cast<uint32_t*>(&p3));
            *reinterpret_cast<uint4*>(Bm + r * BPLD + c) = pk;
        }
        {
            const float4* src = reinterpret_cast<const float4*>(wn + (size_t)r * LF + n0 + c);
            float4 v0 = src[0], v1 = src[1];
            __nv_bfloat162 p0 = __floats2bfloat162_rn(v0.x, v0.y);
            __nv_bfloat162 p1 = __floats2bfloat162_rn(v0.z, v0.w);
            __nv_bfloat162 p2 = __floats2bfloat162_rn(v1.x, v1.y);
            __nv_bfloat162 p3 = __floats2bfloat162_rn(v1.z, v1.w);
            uint4 pk = make_uint4(*reinterpret_cast<uint32_t*>(&p0), *reinterpret_cast<uint32_t*>(&p1),
                                  *reinterpret_cast<uint32_t*>(&p2), *reinterpret_cast<uint32_t*>(&p3));
            *reinterpret_cast<uint4*>(Bn + r * BPLD + c) = pk;
        }
    }
    __syncthreads();

    // ---- GEMMs: 16 warps, each owns 16 rows of M=256 ----
#pragma unroll
    for (int gsel = 0; gsel < 2; gsel++) {
        const __nv_bfloat16* Bt = gsel ? Bn : Bm;
        wmma::fragment<wmma::accumulator, 16, 16, 16, float> acc[4];
#pragma unroll
        for (int ni = 0; ni < 4; ni++) wmma::fill_fragment(acc[ni], 0.0f);
#pragma unroll
        for (int kt = 0; kt < 16; kt++) {
            wmma::fragment<wmma::matrix_a, 16, 16, 16, __nv_bfloat16, wmma::row_major> af;
            wmma::load_matrix_sync(af, Ag + (size_t)(wid * 16) * H2 + kt * 16, H2);
#pragma unroll
            for (int ni = 0; ni < 4; ni++) {
                wmma::fragment<wmma::matrix_b, 16, 16, 16, __nv_bfloat16, wmma::row_major> bf;
                wmma::load_matrix_sync(bf, Bt + (size_t)kt * 16 * BPLD + ni * 16, BPLD);
                wmma::mma_sync(acc[ni], af, bf, acc[ni]);
            }
        }
        float* stg = stage + gsel * 256 * STG;
#pragma unroll
        for (int ni = 0; ni < 4; ni++)
            wmma::store_matrix_sync(stg + (size_t)(wid * 16) * STG + ni * 16, acc[ni], STG, wmma::mem_row_major);
    }
    __syncthreads();

    // ---- fused epilogue (unroll 4 for ILP across threefry chains) ----
    float maskmul = sigmf(*pm) * 0.3f;
    float noisemul = sigmf(*pn) * 0.05f;
    float ss_ = sigmf(*psh);
    float smix = 1.0f - ss_;
    float wa = fminf(fmaxf(1.0f - smix - ss_, 0.1f), 0.8f);
    float wb = smix * 0.5f, wc = ss_ * 0.5f;
    float tot = wa + wb + wc;
    wa /= tot; wb /= tot; wc /= tot;
    uint2 kn = tf2x32(0u, 42u, 0u, 1u);
    const float* gmSb = stage;
    const float* gnSb = stage + 256 * STG;
#pragma unroll 4
    for (int i = tid; i < 16384; i += 512) {
        int r = i >> 6, c = i & 63;
        int b = r;
        int col = n0 + c;
        int f = c, l = l_idx;
        int wpb = swp[b], shb = ssh[b];
        int idx;
        if (shb > 0)      idx = (l >= wpb) ? min(l + shb, LL - 1) : l;
        else if (shb < 0) idx = (l >= wpb + shb && l < LL + shb) ? (l - shb) : l;
        else              idx = l;
        uint32_t e = (uint32_t)b * LF + (uint32_t)col;
        float gm = gmSb[r * STG + c] + sbm[c];
        float mask = 1.0f - (1.0f - sigmf_fast(gm)) * maskmul;
        float gn = gnSb[r * STG + c] + sbn[c];
        float nm = softplusf_fast(gn);
        float nv = tf_normal(kn, e);
        float xv = x[(size_t)e];
        float wv = x[(size_t)b * LF + (size_t)idx * FF + f];
        float fv = g_freq[(size_t)e];
        float sc = g_scale[b * FF + f];
        out[(size_t)e] = (xv * mask * sc + nv * nm * noisemul) * wa + fv * wb + wv * wc;
    }
}

// ---------------- launch ------------------------------------------------------
extern "C" void kernel_launch(void* const* d_in, const int* in_sizes, int n_in,
                              void* d_out, int out_size) {
    const float* x   = (const float*)d_in[0];
    const float* w1  = (const float*)d_in[2];
    const float* b1  = (const float*)d_in[3];
    const float* w2  = (const float*)d_in[4];
    const float* b2  = (const float*)d_in[5];
    const float* w3  = (const float*)d_in[6];
    const float* b3  = (const float*)d_in[7];
    const float* wm  = (const float*)d_in[8];
    const float* bm  = (const float*)d_in[9];
    const float* wn  = (const float*)d_in[10];
    const float* bn  = (const float*)d_in[11];
    const float* ws  = (const float*)d_in[12];
    const float* bs  = (const float*)d_in[13];
    const float* pm  = (const float*)d_in[14];
    const float* pn  = (const float*)d_in[15];
    const float* psh = (const float*)d_in[16];
    const float* psc = (const float*)d_in[17];
    float* out = (float*)d_out;

    cudaFuncSetAttribute(final_mma, cudaFuncAttributeMaxDynamicSharedMemorySize, DYN_SMEM);

    fft_mlp<<<2304, 256>>>(x, w1, b1, w2, b2, w3, b3, ws, bs, psh, psc);
    final_mma<<<512, 512, DYN_SMEM>>>(x, wm, bm, wn, bn, out, pm, pn, psh);
}

// round 13
// speedup vs baseline: 1.3615x; 1.3615x over previous
#include <cuda_runtime.h>
#include <cuda_bf16.h>
#include <mma.h>
#include <cstdint>

using namespace nvcuda;

#define BB   256
#define LL   512
#define FF   64
#define LF   32768
#define NTOT 8388608
#define HH   128
#define H2   256
#define ND   64

// ---------------- device globals ----------------
__device__ __align__(16) uint32_t g_h3b[BB * (H2 / 2)];   // h3 bf16: [256 rows][256]
__device__ float  g_scale[BB * FF];
__device__ float  g_freq[NTOT];

// ---------------- threefry2x32 (JAX) ----------------
__device__ __forceinline__ uint2 tf2x32(uint32_t k0, uint32_t k1, uint32_t x0, uint32_t x1) {
    uint32_t k2 = k0 ^ k1 ^ 0x1BD11BDAu;
    x0 += k0; x1 += k1;
#define TFR(r) { x0 += x1; x1 = (x1 << (r)) | (x1 >> (32 - (r))); x1 ^= x0; }
    TFR(13) TFR(15) TFR(26) TFR(6)
    x0 += k1; x1 += k2 + 1u;
    TFR(17) TFR(29) TFR(16) TFR(24)
    x0 += k2; x1 += k0 + 2u;
    TFR(13) TFR(15) TFR(26) TFR(6)
    x0 += k0; x1 += k1 + 3u;
    TFR(17) TFR(29) TFR(16) TFR(24)
    x0 += k1; x1 += k2 + 4u;
    TFR(13) TFR(15) TFR(26) TFR(6)
    x0 += k2; x1 += k0 + 5u;
#undef TFR
    return make_uint2(x0, x1);
}
__device__ __forceinline__ uint32_t tf_bits(uint2 key, uint32_t e) {
    uint2 r = tf2x32(key.x, key.y, 0u, e);
    return r.x ^ r.y;
}
__device__ __forceinline__ float u01_from_bits(uint32_t bits) {
    return __uint_as_float((bits >> 9) | 0x3f800000u) - 1.0f;
}
__device__ __forceinline__ float tf_normal(uint2 key, uint32_t e) {
    float u = u01_from_bits(tf_bits(key, e));
    const float lo = -0.99999994f;
    float v = u * 2.0f + lo;
    v = fmaxf(lo, v);
    return 1.4142135623730951f * erfinvf(v);
}
__device__ __forceinline__ float sigmf(float x)  { return 1.0f / (1.0f + expf(-x)); }
__device__ __forceinline__ float softplusf(float x) { return fmaxf(x, 0.0f) + log1pf(expf(-fabsf(x))); }
__device__ __forceinline__ float sigmf_fast(float x)  { return __fdividef(1.0f, 1.0f + __expf(-x)); }
__device__ __forceinline__ float softplusf_fast(float x) { return fmaxf(x, 0.0f) + __logf(1.0f + __expf(-fabsf(x))); }

__device__ __forceinline__ float2 cadd(float2 a, float2 b) { return make_float2(a.x + b.x, a.y + b.y); }
__device__ __forceinline__ float2 csub(float2 a, float2 b) { return make_float2(a.x - b.x, a.y - b.y); }
__device__ __forceinline__ float2 cmul(float2 a, float2 w) { return make_float2(a.x * w.x - a.y * w.y, a.x * w.y + a.y * w.x); }
__device__ __forceinline__ float2 cmulc(float2 w, float2 b) { return make_float2(w.x * b.x + w.y * b.y, w.x * b.y - w.y * b.x); }

// ---------------- kernel 1: FFT-aug (blocks 0..2047) + MLP (2048..2303) -----
// (identical to R12 version — measured ~25us faster than R11's)
__global__ __launch_bounds__(256) void fft_mlp(
    const float* __restrict__ x,
    const float* __restrict__ w1, const float* __restrict__ b1,
    const float* __restrict__ w2, const float* __restrict__ b2,
    const float* __restrict__ w3, const float* __restrict__ b3,
    const float* __restrict__ ws, const float* __restrict__ bs,
    const float* __restrict__ psh, const float* __restrict__ psc)
{
    __shared__ float2 s[512][9];
    __shared__ float2 tw[256];
    __shared__ float zb[ND], h1b[HH], h2b[H2], h3b[H2];
    int tid = threadIdx.x;

    if (blockIdx.x >= 2048) {
        int m = blockIdx.x - 2048, t = tid;
        uint2 kz = tf2x32(0u, 42u, 0u, 0u);
        if (t < ND) zb[t] = tf_normal(kz, (uint32_t)(m * ND + t));
        __syncthreads();
        if (t < HH) {
            float acc = b1[t];
#pragma unroll 8
            for (int k = 0; k < ND; k++) acc = fmaf(zb[k], w1[k * HH + t], acc);
            h1b[t] = acc > 0.0f ? acc : 0.2f * acc;
        }
        __syncthreads();
        {
            float acc = b2[t];
#pragma unroll 8
            for (int k = 0; k < HH; k++) acc = fmaf(h1b[k], w2[k * H2 + t], acc);
            h2b[t] = acc > 0.0f ? acc : 0.2f * acc;
        }
        __syncthreads();
        {
            float acc = b3[t];
#pragma unroll 8
            for (int k = 0; k < H2; k++) acc = fmaf(h2b[k], w3[k * H2 + t], acc);
            h3b[t] = acc > 0.0f ? acc : 0.2f * acc;
        }
        __syncthreads();
        if (t < H2 / 2) {
            __nv_bfloat162 p = __floats2bfloat162_rn(h3b[2 * t], h3b[2 * t + 1]);
            g_h3b[m * (H2 / 2) + t] = *reinterpret_cast<uint32_t*>(&p);
        }
        if (t < FF) {
            float s_scale = sigmf(*psc);
            float acc = bs[t];
#pragma unroll 8
            for (int k = 0; k < H2; k++) acc = fmaf(h3b[k], ws[k * FF + t], acc);
            g_scale[m * FF + t] = 1.0f + (softplusf(acc) - 0.5f) * 0.2f * s_scale;
        }
        return;
    }

    float ss_ = sigmf(*psh);
    float smix = 1.0f - ss_;
    float ratio = fminf(smix * 0.1f, 0.5f);
    uint2 kf = tf2x32(0u, 42u, 0u, 4u);

    int bidx = blockIdx.x;
    int b = bidx >> 3;
    int f0 = (bidx & 7) * 8;
    const float* xp = x + (size_t)b * LF + f0;
    {
        float sv, cv;
        sincosf(-6.283185307179586f * (float)tid / 512.0f, &sv, &cv);
        tw[tid] = make_float2(cv, sv);
    }
#pragma unroll
    for (int it = 0; it < 16; it++) {
        int u = it * 256 + tid;
        int ff = u & 7, l = u >> 3;
        s[l][ff] = make_float2(xp[(size_t)l * FF + ff], 0.0f);
    }
    __syncthreads();
#pragma unroll
    for (int st = 0; st < 8; st += 2) {
        const int half  = 256 >> st;
        const int half2 = 128 >> st;
#pragma unroll
        for (int it = 0; it < 4; it++) {
            int u = it * 256 + tid;
            int ff = u & 7, gi = u >> 3;
            int k2 = gi & (half2 - 1);
            int g  = gi >> (7 - st);
            int p0 = (g << (9 - st)) + k2;
            float2 a0 = s[p0][ff], a1 = s[p0 + half2][ff];
            float2 a2 = s[p0 + half][ff], a3 = s[p0 + half + half2][ff];
            float2 w02 = tw[k2 << st];
            float2 w13 = tw[(k2 + half2) << st];
            float2 wnx = tw[k2 << (st + 1)];
            float2 A0 = cadd(a0, a2);
            float2 A2 = cmul(csub(a0, a2), w02);
            float2 A1 = cadd(a1, a3);
            float2 A3 = cmul(csub(a1, a3), w13);
            s[p0][ff]                 = cadd(A0, A1);
            s[p0 + half2][ff]         = cmul(csub(A0, A1), wnx);
            s[p0 + half][ff]          = cadd(A2, A3);
            s[p0 + half + half2][ff]  = cmul(csub(A2, A3), wnx);
        }
        __syncthreads();
    }
#pragma unroll
    for (int it = 0; it < 8; it++) {
        int u = it * 256 + tid;
        int ff = u & 7, bi = u >> 3;
        int p = bi << 1;
        float2 a = s[p][ff], bv = s[p + 1][ff];
        float2 X0 = cadd(a, bv);
        float2 X1 = csub(a, bv);
        int j0 = (int)(__brev((unsigned)p) >> 23);
        int j1 = (int)(__brev((unsigned)(p + 1)) >> 23);
        uint32_t e0 = (uint32_t)b * LF + (uint32_t)j0 * FF + (uint32_t)(f0 + ff);
        uint32_t e1 = (uint32_t)b * LF + (uint32_t)j1 * FF + (uint32_t)(f0 + ff);
        if (!(u01_from_bits(tf_bits(kf, e0)) > ratio)) X0 = make_float2(0.0f, 0.0f);
        if (!(u01_from_bits(tf_bits(kf, e1)) > ratio)) X1 = make_float2(0.0f, 0.0f);
        s[p][ff]     = cadd(X0, X1);
        s[p + 1][ff] = csub(X0, X1);
    }
    __syncthreads();
#pragma unroll
    for (int st = 1; st < 9; st += 2) {
        const int half = 1 << st;
#pragma unroll
        for (int it = 0; it < 4; it++) {
            int u = it * 256 + tid;
            int ff = u & 7, gi = u >> 3;
            int k = gi & (half - 1);
            int g = gi >> st;
            int p0 = (g << (st + 2)) + k;
            float2 a0 = s[p0][ff], a1 = s[p0 + half][ff];
            float2 a2 = s[p0 + 2 * half][ff], a3 = s[p0 + 3 * half][ff];
            float2 wa_ = tw[k << (8 - st)];
            float2 wb_ = tw[k << (7 - st)];
            float2 wc_ = tw[(k + half) << (7 - st)];
            float2 t01 = cmulc(wa_, a1);
            float2 t23 = cmulc(wa_, a3);
            float2 A0 = cadd(a0, t01), A1 = csub(a0, t01);
            float2 A2 = cadd(a2, t23), A3 = csub(a2, t23);
            float2 tB = cmulc(wb_, A2), tC = cmulc(wc_, A3);
            s[p0][ff]             = cadd(A0, tB);
            s[p0 + 2 * half][ff]  = csub(A0, tB);
            s[p0 + half][ff]      = cadd(A1, tC);
            s[p0 + 3 * half][ff]  = csub(A1, tC);
        }
        __syncthreads();
    }
#pragma unroll
    for (int it = 0; it < 16; it++) {
        int u = it * 256 + tid;
        int ff = u & 7, l = u >> 3;
        float val = s[l][ff].x * (1.0f / 512.0f);
        if (smix < 0.01f) val = xp[(size_t)l * FF + ff];
        g_freq[(size_t)b * LF + (size_t)l * FF + f0 + ff] = val;
    }
}

// ---------------- kernel 2: wmma dual GEMM (M=256) + bf16 stage + epilogue --
// smem: [Bm panel | Bn panel | warp scratch]; bf16 stages overwrite dead panels.
// 94 KB dynamic -> 2 CTAs/SM (32 warps).
#define BPLD 72
#define SLD  68                        // bf16 stage leading dim
#define SCR_LD 20                      // per-warp fp32 scratch leading dim
#define PAN_BYTES 36864
#define SCR_OFF   73728
#define DYN_SMEM  (73728 + 16 * 16 * SCR_LD * 4)   // 94208

__global__ __launch_bounds__(512, 2) void final_mma(
    const float* __restrict__ x,
    const float* __restrict__ wm, const float* __restrict__ bmv,
    const float* __restrict__ wn, const float* __restrict__ bnv,
    float* __restrict__ out,
    const float* __restrict__ pm, const float* __restrict__ pn,
    const float* __restrict__ psh)
{
    extern __shared__ char smem[];
    __nv_bfloat16* Bm = reinterpret_cast<__nv_bfloat16*>(smem);
    __nv_bfloat16* Bn = reinterpret_cast<__nv_bfloat16*>(smem + PAN_BYTES);
    float* scratch = reinterpret_cast<float*>(smem + SCR_OFF);
    __shared__ int swp[256], ssh[256];
    __shared__ float sbm[64], sbn[64];
    int tid = threadIdx.x;
    int wid = tid >> 5;
    int lane = tid & 31;
    int n0 = blockIdx.x * 64;
    int l_idx = blockIdx.x;
    const __nv_bfloat16* Ag = reinterpret_cast<const __nv_bfloat16*>(g_h3b);

    // ---- per-CTA wp/sh randint + bias preload ----
    if (tid < 256) {
        float ss_ = sigmf(*psh);
        int ws_ = (int)(51.2f * ss_);
        uint2 kwp = tf2x32(0u, 42u, 0u, 2u);
        uint2 ksh = tf2x32(0u, 42u, 0u, 3u);
        uint2 skwp1 = tf2x32(kwp.x, kwp.y, 0u, 0u);
        uint2 skwp2 = tf2x32(kwp.x, kwp.y, 0u, 1u);
        uint2 sksh1 = tf2x32(ksh.x, ksh.y, 0u, 0u);
        uint2 sksh2 = tf2x32(ksh.x, ksh.y, 0u, 1u);
        {
            uint32_t span = (uint32_t)max(1, (512 - ws_) - ws_);
            uint32_t mult = 65536u % span; mult = (mult * mult) % span;
            uint32_t hi = tf_bits(skwp1, (uint32_t)tid);
            uint32_t lo = tf_bits(skwp2, (uint32_t)tid);
            uint32_t off = ((hi % span) * mult + (lo % span)) % span;
            swp[tid] = ws_ + (int)off;
        }
        {
            uint32_t span = (uint32_t)(2 * ws_ + 1); if (span == 0u) span = 1u;
            uint32_t mult = 65536u % span; mult = (mult * mult) % span;
            uint32_t hi = tf_bits(sksh1, (uint32_t)tid);
            uint32_t lo = tf_bits(sksh2, (uint32_t)tid);
            uint32_t off = ((hi % span) * mult + (lo % span)) % span;
            ssh[tid] = -ws_ + (int)off;
        }
    }
    if (tid >= 256 && tid < 320) { sbm[tid - 256] = bmv[n0 + tid - 256]; }
    if (tid >= 320 && tid < 384) { sbn[tid - 320] = bnv[n0 + tid - 320]; }

    // ---- preload BOTH panels: K=256 x N=64 fp32 -> bf16 smem ----
#pragma unroll
    for (int i = 0; i < 4; i++) {
        int u = i * 512 + tid;
        int r = u >> 3, c = (u & 7) * 8;
        {
            const float4* src = reinterpret_cast<const float4*>(wm + (size_t)r * LF + n0 + c);
            float4 v0 = src[0], v1 = src[1];
            __nv_bfloat162 p0 = __floats2bfloat162_rn(v0.x, v0.y);
            __nv_bfloat162 p1 = __floats2bfloat162_rn(v0.z, v0.w);
            __nv_bfloat162 p2 = __floats2bfloat162_rn(v1.x, v1.y);
            __nv_bfloat162 p3 = __floats2bfloat162_rn(v1.z, v1.w);
            uint4 pk = make_uint4(*reinterpret_cast<uint32_t*>(&p0), *reinterpret_cast<uint32_t*>(&p1),
                                  *reinterpret_cast<uint32_t*>(&p2), *reinterpret_cast<uint32_t*>(&p3));
            *reinterpret_cast<uint4*>(Bm + r * BPLD + c) = pk;
        }
        {
            const float4* src = reinterpret_cast<const float4*>(wn + (size_t)r * LF + n0 + c);
            float4 v0 = src[0], v1 = src[1];
            __nv_bfloat162 p0 = __floats2bfloat162_rn(v0.x, v0.y);
            __nv_bfloat162 p1 = __floats2bfloat162_rn(v0.z, v0.w);
            __nv_bfloat162 p2 = __floats2bfloat162_rn(v1.x, v1.y);
            __nv_bfloat162 p3 = __floats2bfloat162_rn(v1.z, v1.w);
            uint4 pk = make_uint4(*reinterpret_cast<uint32_t*>(&p0), *reinterpret_cast<uint32_t*>(&p1),
                                  *reinterpret_cast<uint32_t*>(&p2), *reinterpret_cast<uint32_t*>(&p3));
            *reinterpret_cast<uint4*>(Bn + r * BPLD + c) = pk;
        }
    }
    __syncthreads();

    // ---- GEMMs; after each, stage logits as bf16 over the dead panel ----
#pragma unroll
    for (int gsel = 0; gsel < 2; gsel++) {
        const __nv_bfloat16* Bt = gsel ? Bn : Bm;
        wmma::fragment<wmma::accumulator, 16, 16, 16, float> acc[4];
#pragma unroll
        for (int ni = 0; ni < 4; ni++) wmma::fill_fragment(acc[ni], 0.0f);
#pragma unroll
        for (int kt = 0; kt < 16; kt++) {
            wmma::fragment<wmma::matrix_a, 16, 16, 16, __nv_bfloat16, wmma::row_major> af;
            wmma::load_matrix_sync(af, Ag + (size_t)(wid * 16) * H2 + kt * 16, H2);
#pragma unroll
            for (int ni = 0; ni < 4; ni++) {
                wmma::fragment<wmma::matrix_b, 16, 16, 16, __nv_bfloat16, wmma::row_major> bf;
                wmma::load_matrix_sync(bf, Bt + (size_t)kt * 16 * BPLD + ni * 16, BPLD);
                wmma::mma_sync(acc[ni], af, bf, acc[ni]);
            }
        }
        __syncthreads();   // all warps done reading this panel; safe to overwrite
        {
            float* scr = scratch + wid * 16 * SCR_LD;
            __nv_bfloat16* stg = (gsel ? Bn : Bm);   // reuse as bf16 stage [256][SLD]
            int row = lane >> 1, cb = (lane & 1) * 8;
#pragma unroll
            for (int ni = 0; ni < 4; ni++) {
                wmma::store_matrix_sync(scr, acc[ni], SCR_LD, wmma::mem_row_major);
                __syncwarp();
                float v0 = scr[row * SCR_LD + cb + 0], v1 = scr[row * SCR_LD + cb + 1];
                float v2 = scr[row * SCR_LD + cb + 2], v3 = scr[row * SCR_LD + cb + 3];
                float v4 = scr[row * SCR_LD + cb + 4], v5 = scr[row * SCR_LD + cb + 5];
                float v6 = scr[row * SCR_LD + cb + 6], v7 = scr[row * SCR_LD + cb + 7];
                __nv_bfloat162 q0 = __floats2bfloat162_rn(v0, v1);
                __nv_bfloat162 q1 = __floats2bfloat162_rn(v2, v3);
                __nv_bfloat162 q2 = __floats2bfloat162_rn(v4, v5);
                __nv_bfloat162 q3 = __floats2bfloat162_rn(v6, v7);
                uint32_t* dst = reinterpret_cast<uint32_t*>(stg + (size_t)(wid * 16 + row) * SLD + ni * 16 + cb);
                uint2 w0 = make_uint2(*reinterpret_cast<uint32_t*>(&q0), *reinterpret_cast<uint32_t*>(&q1));
                uint2 w1 = make_uint2(*reinterpret_cast<uint32_t*>(&q2), *reinterpret_cast<uint32_t*>(&q3));
                *reinterpret_cast<uint2*>(dst)     = w0;
                *reinterpret_cast<uint2*>(dst + 2) = w1;
                __syncwarp();
            }
        }
    }
    __syncthreads();

    // ---- fused epilogue (R11 structure; bf16 stage reads) ----
    float maskmul = sigmf_fast(*pm) * 0.3f;
    float noisemul = sigmf_fast(*pn) * 0.05f;
    float ss_ = sigmf(*psh);
    float smix = 1.0f - ss_;
    float wa = fminf(fmaxf(1.0f - smix - ss_, 0.1f), 0.8f);
    float wb = smix * 0.5f, wc = ss_ * 0.5f;
    float tot = wa + wb + wc;
    wa /= tot; wb /= tot; wc /= tot;
    uint2 kn = tf2x32(0u, 42u, 0u, 1u);
    const __nv_bfloat16* gmSb = Bm;
    const __nv_bfloat16* gnSb = Bn;
    for (int i = tid; i < 16384; i += 512) {
        int r = i >> 6, c = i & 63;
        int b = r;
        int col = n0 + c;
        int f = c, l = l_idx;
        int wpb = swp[b], shb = ssh[b];
        int idx;
        if (shb > 0)      idx = (l >= wpb) ? min(l + shb, LL - 1) : l;
        else if (shb < 0) idx = (l >= wpb + shb && l < LL + shb) ? (l - shb) : l;
        else              idx = l;
        uint32_t e = (uint32_t)b * LF + (uint32_t)col;
        float gm = __bfloat162float(gmSb[r * SLD + c]) + sbm[c];
        float mask = 1.0f - (1.0f - sigmf_fast(gm)) * maskmul;
        float gn = __bfloat162float(gnSb[r * SLD + c]) + sbn[c];
        float nm = softplusf_fast(gn);
        float nv = tf_normal(kn, e);
        float xv = x[(size_t)e];
        float wv = x[(size_t)b * LF + (size_t)idx * FF + f];
        float fv = g_freq[(size_t)e];
        float sc = g_scale[b * FF + f];
        out[(size_t)e] = (xv * mask * sc + nv * nm * noisemul) * wa + fv * wb + wv * wc;
    }
}

// ---------------- launch ------------------------------------------------------
extern "C" void kernel_launch(void* const* d_in, const int* in_sizes, int n_in,
                              void* d_out, int out_size) {
    const float* x   = (const float*)d_in[0];
    const float* w1  = (const float*)d_in[2];
    const float* b1  = (const float*)d_in[3];
    const float* w2  = (const float*)d_in[4];
    const float* b2  = (const float*)d_in[5];
    const float* w3  = (const float*)d_in[6];
    const float* b3  = (const float*)d_in[7];
    const float* wm  = (const float*)d_in[8];
    const float* bm  = (const float*)d_in[9];
    const float* wn  = (const float*)d_in[10];
    const float* bn  = (const float*)d_in[11];
    const float* ws  = (const float*)d_in[12];
    const float* bs  = (const float*)d_in[13];
    const float* pm  = (const float*)d_in[14];
    const float* pn  = (const float*)d_in[15];
    const float* psh = (const float*)d_in[16];
    const float* psc = (const float*)d_in[17];
    float* out = (float*)d_out;

    cudaFuncSetAttribute(final_mma, cudaFuncAttributeMaxDynamicSharedMemorySize, DYN_SMEM);

    fft_mlp<<<2304, 256>>>(x, w1, b1, w2, b2, w3, b3, ws, bs, psh, psc);
    final_mma<<<512, 512, DYN_SMEM>>>(x, wm, bm, wn, bn, out, pm, pn, psh);
}

// round 14
// speedup vs baseline: 1.3631x; 1.0012x over previous
#include <cuda_runtime.h>
#include <cuda_bf16.h>
#include <mma.h>
#include <cstdint>

using namespace nvcuda;

#define BB   256
#define LL   512
#define FF   64
#define LF   32768
#define NTOT 8388608
#define HH   128
#define H2   256
#define ND   64

// ---------------- device globals ----------------
__device__ __align__(16) uint32_t g_h3b[BB * (H2 / 2)];   // h3 bf16: [256 rows][256]
__device__ float  g_scale[BB * FF];
__device__ float  g_freq[NTOT];
__device__ float  g_gm[NTOT];      // mask logits (pre-bias)
__device__ float  g_gn[NTOT];      // noise logits (pre-bias)
__device__ int    g_wp[BB], g_sh[BB];

// ---------------- threefry2x32 (JAX) ----------------
__device__ __forceinline__ uint2 tf2x32(uint32_t k0, uint32_t k1, uint32_t x0, uint32_t x1) {
    uint32_t k2 = k0 ^ k1 ^ 0x1BD11BDAu;
    x0 += k0; x1 += k1;
#define TFR(r) { x0 += x1; x1 = (x1 << (r)) | (x1 >> (32 - (r))); x1 ^= x0; }
    TFR(13) TFR(15) TFR(26) TFR(6)
    x0 += k1; x1 += k2 + 1u;
    TFR(17) TFR(29) TFR(16) TFR(24)
    x0 += k2; x1 += k0 + 2u;
    TFR(13) TFR(15) TFR(26) TFR(6)
    x0 += k0; x1 += k1 + 3u;
    TFR(17) TFR(29) TFR(16) TFR(24)
    x0 += k1; x1 += k2 + 4u;
    TFR(13) TFR(15) TFR(26) TFR(6)
    x0 += k2; x1 += k0 + 5u;
#undef TFR
    return make_uint2(x0, x1);
}
__device__ __forceinline__ uint32_t tf_bits(uint2 key, uint32_t e) {
    uint2 r = tf2x32(key.x, key.y, 0u, e);
    return r.x ^ r.y;
}
__device__ __forceinline__ float u01_from_bits(uint32_t bits) {
    return __uint_as_float((bits >> 9) | 0x3f800000u) - 1.0f;
}
__device__ __forceinline__ float tf_normal(uint2 key, uint32_t e) {
    float u = u01_from_bits(tf_bits(key, e));
    const float lo = -0.99999994f;
    float v = u * 2.0f + lo;
    v = fmaxf(lo, v);
    return 1.4142135623730951f * erfinvf(v);
}
__device__ __forceinline__ float sigmf(float x)  { return 1.0f / (1.0f + expf(-x)); }
__device__ __forceinline__ float softplusf(float x) { return fmaxf(x, 0.0f) + log1pf(expf(-fabsf(x))); }
__device__ __forceinline__ float sigmf_fast(float x)  { return __fdividef(1.0f, 1.0f + __expf(-x)); }
__device__ __forceinline__ float softplusf_fast(float x) { return fmaxf(x, 0.0f) + __logf(1.0f + __expf(-fabsf(x))); }

__device__ __forceinline__ float2 cadd(float2 a, float2 b) { return make_float2(a.x + b.x, a.y + b.y); }
__device__ __forceinline__ float2 csub(float2 a, float2 b) { return make_float2(a.x - b.x, a.y - b.y); }
__device__ __forceinline__ float2 cmul(float2 a, float2 w) { return make_float2(a.x * w.x - a.y * w.y, a.x * w.y + a.y * w.x); }
__device__ __forceinline__ float2 cmulc(float2 w, float2 b) { return make_float2(w.x * b.x + w.y * b.y, w.x * b.y - w.y * b.x); }

// ---------------- kernel 1: FFT (0..2047) + MLP (2048..2303) + setup (2304) -
__global__ __launch_bounds__(256) void fft_mlp(
    const float* __restrict__ x,
    const float* __restrict__ w1, const float* __restrict__ b1,
    const float* __restrict__ w2, const float* __restrict__ b2,
    const float* __restrict__ w3, const float* __restrict__ b3,
    const float* __restrict__ ws, const float* __restrict__ bs,
    const float* __restrict__ psh, const float* __restrict__ psc)
{
    __shared__ float2 s[512][9];
    __shared__ float2 tw[256];
    __shared__ float zb[ND], h1b[HH], h2b[H2], h3b[H2];
    int tid = threadIdx.x;

    if (blockIdx.x >= 2304) {
        // ------- setup: wp/sh randints for the epilogue kernel -------
        float ss_ = sigmf(*psh);
        int ws_ = (int)(51.2f * ss_);
        uint2 kwp = tf2x32(0u, 42u, 0u, 2u);
        uint2 ksh = tf2x32(0u, 42u, 0u, 3u);
        uint2 skwp1 = tf2x32(kwp.x, kwp.y, 0u, 0u);
        uint2 skwp2 = tf2x32(kwp.x, kwp.y, 0u, 1u);
        uint2 sksh1 = tf2x32(ksh.x, ksh.y, 0u, 0u);
        uint2 sksh2 = tf2x32(ksh.x, ksh.y, 0u, 1u);
        {
            uint32_t span = (uint32_t)max(1, (512 - ws_) - ws_);
            uint32_t mult = 65536u % span; mult = (mult * mult) % span;
            uint32_t hi = tf_bits(skwp1, (uint32_t)tid);
            uint32_t lo = tf_bits(skwp2, (uint32_t)tid);
            uint32_t off = ((hi % span) * mult + (lo % span)) % span;
            g_wp[tid] = ws_ + (int)off;
        }
        {
            uint32_t span = (uint32_t)(2 * ws_ + 1); if (span == 0u) span = 1u;
            uint32_t mult = 65536u % span; mult = (mult * mult) % span;
            uint32_t hi = tf_bits(sksh1, (uint32_t)tid);
            uint32_t lo = tf_bits(sksh2, (uint32_t)tid);
            uint32_t off = ((hi % span) * mult + (lo % span)) % span;
            g_sh[tid] = -ws_ + (int)off;
        }
        return;
    }

    if (blockIdx.x >= 2048) {
        // ------- MLP path -------
        int m = blockIdx.x - 2048, t = tid;
        uint2 kz = tf2x32(0u, 42u, 0u, 0u);
        if (t < ND) zb[t] = tf_normal(kz, (uint32_t)(m * ND + t));
        __syncthreads();
        if (t < HH) {
            float acc = b1[t];
#pragma unroll 8
            for (int k = 0; k < ND; k++) acc = fmaf(zb[k], w1[k * HH + t], acc);
            h1b[t] = acc > 0.0f ? acc : 0.2f * acc;
        }
        __syncthreads();
        {
            float acc = b2[t];
#pragma unroll 8
            for (int k = 0; k < HH; k++) acc = fmaf(h1b[k], w2[k * H2 + t], acc);
            h2b[t] = acc > 0.0f ? acc : 0.2f * acc;
        }
        __syncthreads();
        {
            float acc = b3[t];
#pragma unroll 8
            for (int k = 0; k < H2; k++) acc = fmaf(h2b[k], w3[k * H2 + t], acc);
            h3b[t] = acc > 0.0f ? acc : 0.2f * acc;
        }
        __syncthreads();
        if (t < H2 / 2) {
            __nv_bfloat162 p = __floats2bfloat162_rn(h3b[2 * t], h3b[2 * t + 1]);
            g_h3b[m * (H2 / 2) + t] = *reinterpret_cast<uint32_t*>(&p);
        }
        if (t < FF) {
            float s_scale = sigmf(*psc);
            float acc = bs[t];
#pragma unroll 8
            for (int k = 0; k < H2; k++) acc = fmaf(h3b[k], ws[k * FF + t], acc);
            g_scale[m * FF + t] = 1.0f + (softplusf(acc) - 0.5f) * 0.2f * s_scale;
        }
        return;
    }

    // ------- FFT path -------
    float ss_ = sigmf(*psh);
    float smix = 1.0f - ss_;
    float ratio = fminf(smix * 0.1f, 0.5f);
    uint2 kf = tf2x32(0u, 42u, 0u, 4u);

    int bidx = blockIdx.x;
    int b = bidx >> 3;
    int f0 = (bidx & 7) * 8;
    const float* xp = x + (size_t)b * LF + f0;
    {
        float sv, cv;
        sincosf(-6.283185307179586f * (float)tid / 512.0f, &sv, &cv);
        tw[tid] = make_float2(cv, sv);
    }
    // float4 vectorized load: 2 float4 per row of 8 columns
#pragma unroll
    for (int it = 0; it < 4; it++) {
        int c4 = it * 256 + tid;            // 1024 float4 chunks
        int l = c4 >> 1, q = (c4 & 1) * 4;
        float4 v = *reinterpret_cast<const float4*>(xp + (size_t)l * FF + q);
        s[l][q + 0] = make_float2(v.x, 0.0f);
        s[l][q + 1] = make_float2(v.y, 0.0f);
        s[l][q + 2] = make_float2(v.z, 0.0f);
        s[l][q + 3] = make_float2(v.w, 0.0f);
    }
    __syncthreads();
#pragma unroll
    for (int st = 0; st < 8; st += 2) {
        const int half  = 256 >> st;
        const int half2 = 128 >> st;
#pragma unroll
        for (int it = 0; it < 4; it++) {
            int u = it * 256 + tid;
            int ff = u & 7, gi = u >> 3;
            int k2 = gi & (half2 - 1);
            int g  = gi >> (7 - st);
            int p0 = (g << (9 - st)) + k2;
            float2 a0 = s[p0][ff], a1 = s[p0 + half2][ff];
            float2 a2 = s[p0 + half][ff], a3 = s[p0 + half + half2][ff];
            float2 w02 = tw[k2 << st];
            float2 w13 = tw[(k2 + half2) << st];
            float2 wnx = tw[k2 << (st + 1)];
            float2 A0 = cadd(a0, a2);
            float2 A2 = cmul(csub(a0, a2), w02);
            float2 A1 = cadd(a1, a3);
            float2 A3 = cmul(csub(a1, a3), w13);
            s[p0][ff]                 = cadd(A0, A1);
            s[p0 + half2][ff]         = cmul(csub(A0, A1), wnx);
            s[p0 + half][ff]          = cadd(A2, A3);
            s[p0 + half + half2][ff]  = cmul(csub(A2, A3), wnx);
        }
        __syncthreads();
    }
#pragma unroll
    for (int it = 0; it < 8; it++) {
        int u = it * 256 + tid;
        int ff = u & 7, bi = u >> 3;
        int p = bi << 1;
        float2 a = s[p][ff], bv = s[p + 1][ff];
        float2 X0 = cadd(a, bv);
        float2 X1 = csub(a, bv);
        int j0 = (int)(__brev((unsigned)p) >> 23);
        int j1 = (int)(__brev((unsigned)(p + 1)) >> 23);
        uint32_t e0 = (uint32_t)b * LF + (uint32_t)j0 * FF + (uint32_t)(f0 + ff);
        uint32_t e1 = (uint32_t)b * LF + (uint32_t)j1 * FF + (uint32_t)(f0 + ff);
        if (!(u01_from_bits(tf_bits(kf, e0)) > ratio)) X0 = make_float2(0.0f, 0.0f);
        if (!(u01_from_bits(tf_bits(kf, e1)) > ratio)) X1 = make_float2(0.0f, 0.0f);
        s[p][ff]     = cadd(X0, X1);
        s[p + 1][ff] = csub(X0, X1);
    }
    __syncthreads();
#pragma unroll
    for (int st = 1; st < 9; st += 2) {
        const int half = 1 << st;
#pragma unroll
        for (int it = 0; it < 4; it++) {
            int u = it * 256 + tid;
            int ff = u & 7, gi = u >> 3;
            int k = gi & (half - 1);
            int g = gi >> st;
            int p0 = (g << (st + 2)) + k;
            float2 a0 = s[p0][ff], a1 = s[p0 + half][ff];
            float2 a2 = s[p0 + 2 * half][ff], a3 = s[p0 + 3 * half][ff];
            float2 wa_ = tw[k << (8 - st)];
            float2 wb_ = tw[k << (7 - st)];
            float2 wc_ = tw[(k + half) << (7 - st)];
            float2 t01 = cmulc(wa_, a1);
            float2 t23 = cmulc(wa_, a3);
            float2 A0 = cadd(a0, t01), A1 = csub(a0, t01);
            float2 A2 = cadd(a2, t23), A3 = csub(a2, t23);
            float2 tB = cmulc(wb_, A2), tC = cmulc(wc_, A3);
            s[p0][ff]             = cadd(A0, tB);
            s[p0 + 2 * half][ff]  = csub(A0, tB);
            s[p0 + half][ff]      = cadd(A1, tC);
            s[p0 + 3 * half][ff]  = csub(A1, tC);
        }
        __syncthreads();
    }
    // float4 vectorized store
#pragma unroll
    for (int it = 0; it < 4; it++) {
        int c4 = it * 256 + tid;
        int l = c4 >> 1, q = (c4 & 1) * 4;
        float4 v;
        v.x = s[l][q + 0].x * (1.0f / 512.0f);
        v.y = s[l][q + 1].x * (1.0f / 512.0f);
        v.z = s[l][q + 2].x * (1.0f / 512.0f);
        v.w = s[l][q + 3].x * (1.0f / 512.0f);
        if (smix < 0.01f) v = *reinterpret_cast<const float4*>(xp + (size_t)l * FF + q);
        *reinterpret_cast<float4*>(&g_freq[(size_t)b * LF + (size_t)l * FF + f0 + q]) = v;
    }
}

// ---------------- kernel 2: pure wmma dual GEMM -> fp32 logits in global ----
#define BPLD 72
#define PAN_BYTES 36864
#define DYN_SMEM  (2 * PAN_BYTES)       // 73728

__global__ __launch_bounds__(512, 2) void gemm_kernel(
    const float* __restrict__ wm, const float* __restrict__ wn)
{
    extern __shared__ char smem[];
    __nv_bfloat16* Bm = reinterpret_cast<__nv_bfloat16*>(smem);
    __nv_bfloat16* Bn = reinterpret_cast<__nv_bfloat16*>(smem + PAN_BYTES);
    int tid = threadIdx.x;
    int wid = tid >> 5;
    int n0 = blockIdx.x * 64;
    const __nv_bfloat16* Ag = reinterpret_cast<const __nv_bfloat16*>(g_h3b);

#pragma unroll
    for (int i = 0; i < 4; i++) {
        int u = i * 512 + tid;
        int r = u >> 3, c = (u & 7) * 8;
        {
            const float4* src = reinterpret_cast<const float4*>(wm + (size_t)r * LF + n0 + c);
            float4 v0 = src[0], v1 = src[1];
            __nv_bfloat162 p0 = __floats2bfloat162_rn(v0.x, v0.y);
            __nv_bfloat162 p1 = __floats2bfloat162_rn(v0.z, v0.w);
            __nv_bfloat162 p2 = __floats2bfloat162_rn(v1.x, v1.y);
            __nv_bfloat162 p3 = __floats2bfloat162_rn(v1.z, v1.w);
            uint4 pk = make_uint4(*reinterpret_cast<uint32_t*>(&p0), *reinterpret_cast<uint32_t*>(&p1),
                                  *reinterpret_cast<uint32_t*>(&p2), *reinterpret_cast<uint32_t*>(&p3));
            *reinterpret_cast<uint4*>(Bm + r * BPLD + c) = pk;
        }
        {
            const float4* src = reinterpret_cast<const float4*>(wn + (size_t)r * LF + n0 + c);
            float4 v0 = src[0], v1 = src[1];
            __nv_bfloat162 p0 = __floats2bfloat162_rn(v0.x, v0.y);
            __nv_bfloat162 p1 = __floats2bfloat162_rn(v0.z, v0.w);
            __nv_bfloat162 p2 = __floats2bfloat162_rn(v1.x, v1.y);
            __nv_bfloat162 p3 = __floats2bfloat162_rn(v1.z, v1.w);
            uint4 pk = make_uint4(*reinterpret_cast<uint32_t*>(&p0), *reinterpret_cast<uint32_t*>(&p1),
                                  *reinterpret_cast<uint32_t*>(&p2), *reinterpret_cast<uint32_t*>(&p3));
            *reinterpret_cast<uint4*>(Bn + r * BPLD + c) = pk;
        }
    }
    __syncthreads();

#pragma unroll
    for (int gsel = 0; gsel < 2; gsel++) {
        const __nv_bfloat16* Bt = gsel ? Bn : Bm;
        float* dst = gsel ? g_gn : g_gm;
        wmma::fragment<wmma::accumulator, 16, 16, 16, float> acc[4];
#pragma unroll
        for (int ni = 0; ni < 4; ni++) wmma::fill_fragment(acc[ni], 0.0f);
#pragma unroll
        for (int kt = 0; kt < 16; kt++) {
            wmma::fragment<wmma::matrix_a, 16, 16, 16, __nv_bfloat16, wmma::row_major> af;
            wmma::load_matrix_sync(af, Ag + (size_t)(wid * 16) * H2 + kt * 16, H2);
#pragma unroll
            for (int ni = 0; ni < 4; ni++) {
                wmma::fragment<wmma::matrix_b, 16, 16, 16, __nv_bfloat16, wmma::row_major> bf;
                wmma::load_matrix_sync(bf, Bt + (size_t)kt * 16 * BPLD + ni * 16, BPLD);
                wmma::mma_sync(acc[ni], af, bf, acc[ni]);
            }
        }
        // store directly to global, row-major [256][32768]
#pragma unroll
        for (int ni = 0; ni < 4; ni++)
            wmma::store_matrix_sync(dst + (size_t)(wid * 16) * LF + n0 + ni * 16,
                                    acc[ni], LF, wmma::mem_row_major);
    }
}

// ---------------- kernel 3: high-occupancy fused epilogue -------------------
// 4096 blocks x 256 threads; each block covers 2048 consecutive elements (one b).
__global__ __launch_bounds__(256) void epilogue_kernel(
    const float* __restrict__ x,
    const float* __restrict__ bmv, const float* __restrict__ bnv,
    float* __restrict__ out,
    const float* __restrict__ pm, const float* __restrict__ pn,
    const float* __restrict__ psh)
{
    int tid = threadIdx.x;
    int bid = blockIdx.x;
    int b = bid >> 4;                          // 16 blocks per batch row
    uint32_t base = (uint32_t)bid * 2048u;
    int wpb = g_wp[b], shb = g_sh[b];

    float maskmul = sigmf_fast(*pm) * 0.3f;
    float noisemul = sigmf_fast(*pn) * 0.05f;
    float ss_ = sigmf(*psh);
    float smix = 1.0f - ss_;
    float wa = fminf(fmaxf(1.0f - smix - ss_, 0.1f), 0.8f);
    float wb = smix * 0.5f, wc = ss_ * 0.5f;
    float tot = wa + wb + wc;
    wa /= tot; wb /= tot; wc /= tot;
    uint2 kn = tf2x32(0u, 42u, 0u, 1u);

#pragma unroll
    for (int k = 0; k < 8; k++) {
        uint32_t e = base + (uint32_t)(k * 256 + tid);
        int col = (int)(e & 32767u);
        int l = col >> 6, f = col & 63;
        int idx;
        if (shb > 0)      idx = (l >= wpb) ? min(l + shb, LL - 1) : l;
        else if (shb < 0) idx = (l >= wpb + shb && l < LL + shb) ? (l - shb) : l;
        else              idx = l;
        float gm = g_gm[e] + bmv[col];
        float mask = 1.0f - (1.0f - sigmf_fast(gm)) * maskmul;
        float gn = g_gn[e] + bnv[col];
        float nm = softplusf_fast(gn);
        float nv = tf_normal(kn, e);
        float xv = x[(size_t)e];
        float wv = x[(size_t)b * LF + (size_t)idx * FF + f];
        float fv = g_freq[(size_t)e];
        float sc = g_scale[b * FF + f];
        out[(size_t)e] = (xv * mask * sc + nv * nm * noisemul) * wa + fv * wb + wv * wc;
    }
}

// ---------------- launch ------------------------------------------------------
extern "C" void kernel_launch(void* const* d_in, const int* in_sizes, int n_in,
                              void* d_out, int out_size) {
    const float* x   = (const float*)d_in[0];
    const float* w1  = (const float*)d_in[2];
    const float* b1  = (const float*)d_in[3];
    const float* w2  = (const float*)d_in[4];
    const float* b2  = (const float*)d_in[5];
    const float* w3  = (const float*)d_in[6];
    const float* b3  = (const float*)d_in[7];
    const float* wm  = (const float*)d_in[8];
    const float* bm  = (const float*)d_in[9];
    const float* wn  = (const float*)d_in[10];
    const float* bn  = (const float*)d_in[11];
    const float* ws  = (const float*)d_in[12];
    const float* bs  = (const float*)d_in[13];
    const float* pm  = (const float*)d_in[14];
    const float* pn  = (const float*)d_in[15];
    const float* psh = (const float*)d_in[16];
    const float* psc = (const float*)d_in[17];
    float* out = (float*)d_out;

    cudaFuncSetAttribute(gemm_kernel, cudaFuncAttributeMaxDynamicSharedMemorySize, DYN_SMEM);

    fft_mlp<<<2305, 256>>>(x, w1, b1, w2, b2, w3, b3, ws, bs, psh, psc);
    gemm_kernel<<<512, 512, DYN_SMEM>>>(wm, wn);
    epilogue_kernel<<<4096, 256>>>(x, bm, bn, out, pm, pn, psh);
}

// round 15
// speedup vs baseline: 1.5103x; 1.1080x over previous
#include <cuda_runtime.h>
#include <cuda_bf16.h>
#include <mma.h>
#include <cstdint>

using namespace nvcuda;

#define BB   256
#define LL   512
#define FF   64
#define LF   32768
#define NTOT 8388608
#define HH   128
#define H2   256
#define ND   64

// ---------------- device globals ----------------
__device__ __align__(16) uint32_t g_h3b[BB * (H2 / 2)];   // h3 bf16: [256 rows][256]
__device__ float  g_scale[BB * FF];
__device__ float  g_freq[NTOT];
__device__ float  g_gm[NTOT];      // mask logits (pre-bias)
__device__ float  g_gn[NTOT];      // noise logits (pre-bias)
__device__ int    g_wp[BB], g_sh[BB];

// ---------------- threefry2x32 (JAX) ----------------
__device__ __forceinline__ uint2 tf2x32(uint32_t k0, uint32_t k1, uint32_t x0, uint32_t x1) {
    uint32_t k2 = k0 ^ k1 ^ 0x1BD11BDAu;
    x0 += k0; x1 += k1;
#define TFR(r) { x0 += x1; x1 = (x1 << (r)) | (x1 >> (32 - (r))); x1 ^= x0; }
    TFR(13) TFR(15) TFR(26) TFR(6)
    x0 += k1; x1 += k2 + 1u;
    TFR(17) TFR(29) TFR(16) TFR(24)
    x0 += k2; x1 += k0 + 2u;
    TFR(13) TFR(15) TFR(26) TFR(6)
    x0 += k0; x1 += k1 + 3u;
    TFR(17) TFR(29) TFR(16) TFR(24)
    x0 += k1; x1 += k2 + 4u;
    TFR(13) TFR(15) TFR(26) TFR(6)
    x0 += k2; x1 += k0 + 5u;
#undef TFR
    return make_uint2(x0, x1);
}
__device__ __forceinline__ uint32_t tf_bits(uint2 key, uint32_t e) {
    uint2 r = tf2x32(key.x, key.y, 0u, e);
    return r.x ^ r.y;
}
__device__ __forceinline__ float u01_from_bits(uint32_t bits) {
    return __uint_as_float((bits >> 9) | 0x3f800000u) - 1.0f;
}
__device__ __forceinline__ float tf_normal(uint2 key, uint32_t e) {
    float u = u01_from_bits(tf_bits(key, e));
    const float lo = -0.99999994f;
    float v = u * 2.0f + lo;
    v = fmaxf(lo, v);
    return 1.4142135623730951f * erfinvf(v);
}
__device__ __forceinline__ float sigmf(float x)  { return 1.0f / (1.0f + expf(-x)); }
__device__ __forceinline__ float softplusf(float x) { return fmaxf(x, 0.0f) + log1pf(expf(-fabsf(x))); }
__device__ __forceinline__ float sigmf_fast(float x)  { return __fdividef(1.0f, 1.0f + __expf(-x)); }
__device__ __forceinline__ float softplusf_fast(float x) { return fmaxf(x, 0.0f) + __logf(1.0f + __expf(-fabsf(x))); }

__device__ __forceinline__ float2 cadd(float2 a, float2 b) { return make_float2(a.x + b.x, a.y + b.y); }
__device__ __forceinline__ float2 csub(float2 a, float2 b) { return make_float2(a.x - b.x, a.y - b.y); }
__device__ __forceinline__ float2 cmul(float2 a, float2 w) { return make_float2(a.x * w.x - a.y * w.y, a.x * w.y + a.y * w.x); }
__device__ __forceinline__ float2 cmulc(float2 w, float2 b) { return make_float2(w.x * b.x + w.y * b.y, w.x * b.y - w.y * b.x); }

// ---------------- kernel 1: FFT (0..2047) + MLP (2048..2303) + setup (2304) -
__global__ __launch_bounds__(256) void fft_mlp(
    const float* __restrict__ x,
    const float* __restrict__ w1, const float* __restrict__ b1,
    const float* __restrict__ w2, const float* __restrict__ b2,
    const float* __restrict__ w3, const float* __restrict__ b3,
    const float* __restrict__ ws, const float* __restrict__ bs,
    const float* __restrict__ psh, const float* __restrict__ psc)
{
    __shared__ float2 s[512][9];
    __shared__ float2 tw[256];
    __shared__ float zb[ND], h1b[HH], h2b[H2], h3b[H2];
    int tid = threadIdx.x;

    if (blockIdx.x >= 2304) {
        // ------- setup: wp/sh randints -------
        float ss_ = sigmf(*psh);
        int ws_ = (int)(51.2f * ss_);
        uint2 kwp = tf2x32(0u, 42u, 0u, 2u);
        uint2 ksh = tf2x32(0u, 42u, 0u, 3u);
        uint2 skwp1 = tf2x32(kwp.x, kwp.y, 0u, 0u);
        uint2 skwp2 = tf2x32(kwp.x, kwp.y, 0u, 1u);
        uint2 sksh1 = tf2x32(ksh.x, ksh.y, 0u, 0u);
        uint2 sksh2 = tf2x32(ksh.x, ksh.y, 0u, 1u);
        {
            uint32_t span = (uint32_t)max(1, (512 - ws_) - ws_);
            uint32_t mult = 65536u % span; mult = (mult * mult) % span;
            uint32_t hi = tf_bits(skwp1, (uint32_t)tid);
            uint32_t lo = tf_bits(skwp2, (uint32_t)tid);
            uint32_t off = ((hi % span) * mult + (lo % span)) % span;
            g_wp[tid] = ws_ + (int)off;
        }
        {
            uint32_t span = (uint32_t)(2 * ws_ + 1); if (span == 0u) span = 1u;
            uint32_t mult = 65536u % span; mult = (mult * mult) % span;
            uint32_t hi = tf_bits(sksh1, (uint32_t)tid);
            uint32_t lo = tf_bits(sksh2, (uint32_t)tid);
            uint32_t off = ((hi % span) * mult + (lo % span)) % span;
            g_sh[tid] = -ws_ + (int)off;
        }
        return;
    }

    if (blockIdx.x >= 2048) {
        // ------- MLP path -------
        int m = blockIdx.x - 2048, t = tid;
        uint2 kz = tf2x32(0u, 42u, 0u, 0u);
        if (t < ND) zb[t] = tf_normal(kz, (uint32_t)(m * ND + t));
        __syncthreads();
        if (t < HH) {
            float acc = b1[t];
#pragma unroll 8
            for (int k = 0; k < ND; k++) acc = fmaf(zb[k], w1[k * HH + t], acc);
            h1b[t] = acc > 0.0f ? acc : 0.2f * acc;
        }
        __syncthreads();
        {
            float acc = b2[t];
#pragma unroll 8
            for (int k = 0; k < HH; k++) acc = fmaf(h1b[k], w2[k * H2 + t], acc);
            h2b[t] = acc > 0.0f ? acc : 0.2f * acc;
        }
        __syncthreads();
        {
            float acc = b3[t];
#pragma unroll 8
            for (int k = 0; k < H2; k++) acc = fmaf(h2b[k], w3[k * H2 + t], acc);
            h3b[t] = acc > 0.0f ? acc : 0.2f * acc;
        }
        __syncthreads();
        if (t < H2 / 2) {
            __nv_bfloat162 p = __floats2bfloat162_rn(h3b[2 * t], h3b[2 * t + 1]);
            g_h3b[m * (H2 / 2) + t] = *reinterpret_cast<uint32_t*>(&p);
        }
        if (t < FF) {
            float s_scale = sigmf(*psc);
            float acc = bs[t];
#pragma unroll 8
            for (int k = 0; k < H2; k++) acc = fmaf(h3b[k], ws[k * FF + t], acc);
            g_scale[m * FF + t] = 1.0f + (softplusf(acc) - 0.5f) * 0.2f * s_scale;
        }
        return;
    }

    // ------- FFT path: radix-8 rounds (3 stages per smem round) -------
    float ss_ = sigmf(*psh);
    float smix = 1.0f - ss_;
    float ratio = fminf(smix * 0.1f, 0.5f);
    uint2 kf = tf2x32(0u, 42u, 0u, 4u);

    int bidx = blockIdx.x;
    int b = bidx >> 3;
    int f0 = (bidx & 7) * 8;
    const float* xp = x + (size_t)b * LF + f0;
    {
        float sv, cv;
        sincosf(-6.283185307179586f * (float)tid / 512.0f, &sv, &cv);
        tw[tid] = make_float2(cv, sv);
    }
#pragma unroll
    for (int it = 0; it < 4; it++) {
        int c4 = it * 256 + tid;
        int l = c4 >> 1, q = (c4 & 1) * 4;
        float4 v = *reinterpret_cast<const float4*>(xp + (size_t)l * FF + q);
        s[l][q + 0] = make_float2(v.x, 0.0f);
        s[l][q + 1] = make_float2(v.y, 0.0f);
        s[l][q + 2] = make_float2(v.z, 0.0f);
        s[l][q + 3] = make_float2(v.w, 0.0f);
    }
    __syncthreads();

    // forward DIF: triples (0,1,2),(3,4,5),(6,7,8). natural in -> bit-rev out.
#pragma unroll
    for (int st = 0; st < 9; st += 3) {
        const int h4 = 64 >> st;
#pragma unroll
        for (int it = 0; it < 2; it++) {
            int u = it * 256 + tid;           // [0,512): 64 groups x 8 cols
            int ff = u & 7, gi = u >> 3;      // gi in [0,64)
            int k = gi & (h4 - 1);
            int g = gi >> (6 - st);
            int p = (g << (9 - st)) + k;
            float2 v[8];
#pragma unroll
            for (int j = 0; j < 8; j++) v[j] = s[p + j * h4][ff];
            // L1: stage st, pairs (j, j+4)
#pragma unroll
            for (int j = 0; j < 4; j++) {
                float2 a = v[j], bb = v[j + 4];
                v[j]     = cadd(a, bb);
                v[j + 4] = cmul(csub(a, bb), tw[(k + j * h4) << st]);
            }
            // L2: stage st+1, pairs (j, j+2) for j in {0,1,4,5}
#pragma unroll
            for (int jj = 0; jj < 4; jj++) {
                int j = (jj >> 1) * 4 + (jj & 1);     // 0,1,4,5
                float2 a = v[j], bb = v[j + 2];
                v[j]     = cadd(a, bb);
                v[j + 2] = cmul(csub(a, bb), tw[(k + (j & 1) * h4) << (st + 1)]);
            }
            // L3: stage st+2, pairs (j, j+1) for even j
#pragma unroll
            for (int jj = 0; jj < 4; jj++) {
                int j = jj * 2;
                float2 a = v[j], bb = v[j + 1];
                v[j]     = cadd(a, bb);
                v[j + 1] = cmul(csub(a, bb), tw[k << (st + 2)]);
            }
#pragma unroll
            for (int j = 0; j < 8; j++) s[p + j * h4][ff] = v[j];
        }
        __syncthreads();
    }

    // inverse DIT: triples (0,1,2),(3,4,5),(6,7,8); mask fused into first triple's load.
#pragma unroll
    for (int st = 0; st < 9; st += 3) {
        const int h = 1 << st;
#pragma unroll
        for (int it = 0; it < 2; it++) {
            int u = it * 256 + tid;
            int ff = u & 7, gi = u >> 3;
            int k = gi & (h - 1);
            int g = gi >> st;
            int p = (g << (st + 3)) + k;
            float2 v[8];
#pragma unroll
            for (int j = 0; j < 8; j++) v[j] = s[p + j * h][ff];
            if (st == 0) {
                // keep-mask at bit-reversed positions q = p + j
#pragma unroll
                for (int j = 0; j < 8; j++) {
                    int q = p + j;
                    int jn = (int)(__brev((unsigned)q) >> 23);
                    uint32_t e = (uint32_t)b * LF + (uint32_t)jn * FF + (uint32_t)(f0 + ff);
                    if (!(u01_from_bits(tf_bits(kf, e)) > ratio)) v[j] = make_float2(0.0f, 0.0f);
                }
            }
            // L1: stage st, pairs (j, j+1) even j; t = conj(w)*b
#pragma unroll
            for (int jj = 0; jj < 4; jj++) {
                int j = jj * 2;
                float2 a = v[j];
                float2 t = cmulc(tw[k << (8 - st)], v[j + 1]);
                v[j]     = cadd(a, t);
                v[j + 1] = csub(a, t);
            }
            // L2: stage st+1, pairs (j, j+2) for j in {0,1,4,5}
#pragma unroll
            for (int jj = 0; jj < 4; jj++) {
                int j = (jj >> 1) * 4 + (jj & 1);
                float2 a = v[j];
                float2 t = cmulc(tw[(k + (j & 1) * h) << (7 - st)], v[j + 2]);
                v[j]     = cadd(a, t);
                v[j + 2] = csub(a, t);
            }
            // L3: stage st+2, pairs (j, j+4), j=0..3
#pragma unroll
            for (int j = 0; j < 4; j++) {
                float2 a = v[j];
                float2 t = cmulc(tw[(k + j * h) << (6 - st)], v[j + 4]);
                v[j]     = cadd(a, t);
                v[j + 4] = csub(a, t);
            }
#pragma unroll
            for (int j = 0; j < 8; j++) s[p + j * h][ff] = v[j];
        }
        __syncthreads();
    }

#pragma unroll
    for (int it = 0; it < 4; it++) {
        int c4 = it * 256 + tid;
        int l = c4 >> 1, q = (c4 & 1) * 4;
        float4 v;
        v.x = s[l][q + 0].x * (1.0f / 512.0f);
        v.y = s[l][q + 1].x * (1.0f / 512.0f);
        v.z = s[l][q + 2].x * (1.0f / 512.0f);
        v.w = s[l][q + 3].x * (1.0f / 512.0f);
        if (smix < 0.01f) v = *reinterpret_cast<const float4*>(xp + (size_t)l * FF + q);
        *reinterpret_cast<float4*>(&g_freq[(size_t)b * LF + (size_t)l * FF + f0 + q]) = v;
    }
}

// ---------------- kernel 2: pure wmma dual GEMM -> fp32 logits in global ----
#define BPLD 72
#define PAN_BYTES 36864
#define DYN_SMEM  (2 * PAN_BYTES)       // 73728

__global__ __launch_bounds__(512, 2) void gemm_kernel(
    const float* __restrict__ wm, const float* __restrict__ wn)
{
    extern __shared__ char smem[];
    __nv_bfloat16* Bm = reinterpret_cast<__nv_bfloat16*>(smem);
    __nv_bfloat16* Bn = reinterpret_cast<__nv_bfloat16*>(smem + PAN_BYTES);
    int tid = threadIdx.x;
    int wid = tid >> 5;
    int n0 = blockIdx.x * 64;
    const __nv_bfloat16* Ag = reinterpret_cast<const __nv_bfloat16*>(g_h3b);

#pragma unroll
    for (int i = 0; i < 4; i++) {
        int u = i * 512 + tid;
        int r = u >> 3, c = (u & 7) * 8;
        {
            const float4* src = reinterpret_cast<const float4*>(wm + (size_t)r * LF + n0 + c);
            float4 v0 = src[0], v1 = src[1];
            __nv_bfloat162 p0 = __floats2bfloat162_rn(v0.x, v0.y);
            __nv_bfloat162 p1 = __floats2bfloat162_rn(v0.z, v0.w);
            __nv_bfloat162 p2 = __floats2bfloat162_rn(v1.x, v1.y);
            __nv_bfloat162 p3 = __floats2bfloat162_rn(v1.z, v1.w);
            uint4 pk = make_uint4(*reinterpret_cast<uint32_t*>(&p0), *reinterpret_cast<uint32_t*>(&p1),
                                  *reinterpret_cast<uint32_t*>(&p2), *reinterpret_cast<uint32_t*>(&p3));
            *reinterpret_cast<uint4*>(Bm + r * BPLD + c) = pk;
        }
        {
            const float4* src = reinterpret_cast<const float4*>(wn + (size_t)r * LF + n0 + c);
            float4 v0 = src[0], v1 = src[1];
            __nv_bfloat162 p0 = __floats2bfloat162_rn(v0.x, v0.y);
            __nv_bfloat162 p1 = __floats2bfloat162_rn(v0.z, v0.w);
            __nv_bfloat162 p2 = __floats2bfloat162_rn(v1.x, v1.y);
            __nv_bfloat162 p3 = __floats2bfloat162_rn(v1.z, v1.w);
            uint4 pk = make_uint4(*reinterpret_cast<uint32_t*>(&p0), *reinterpret_cast<uint32_t*>(&p1),
                                  *reinterpret_cast<uint32_t*>(&p2), *reinterpret_cast<uint32_t*>(&p3));
            *reinterpret_cast<uint4*>(Bn + r * BPLD + c) = pk;
        }
    }
    __syncthreads();

#pragma unroll
    for (int gsel = 0; gsel < 2; gsel++) {
        const __nv_bfloat16* Bt = gsel ? Bn : Bm;
        float* dst = gsel ? g_gn : g_gm;
        wmma::fragment<wmma::accumulator, 16, 16, 16, float> acc[4];
#pragma unroll
        for (int ni = 0; ni < 4; ni++) wmma::fill_fragment(acc[ni], 0.0f);
#pragma unroll
        for (int kt = 0; kt < 16; kt++) {
            wmma::fragment<wmma::matrix_a, 16, 16, 16, __nv_bfloat16, wmma::row_major> af;
            wmma::load_matrix_sync(af, Ag + (size_t)(wid * 16) * H2 + kt * 16, H2);
#pragma unroll
            for (int ni = 0; ni < 4; ni++) {
                wmma::fragment<wmma::matrix_b, 16, 16, 16, __nv_bfloat16, wmma::row_major> bf;
                wmma::load_matrix_sync(bf, Bt + (size_t)kt * 16 * BPLD + ni * 16, BPLD);
                wmma::mma_sync(acc[ni], af, bf, acc[ni]);
            }
        }
#pragma unroll
        for (int ni = 0; ni < 4; ni++)
            wmma::store_matrix_sync(dst + (size_t)(wid * 16) * LF + n0 + ni * 16,
                                    acc[ni], LF, wmma::mem_row_major);
    }
}

// ---------------- kernel 3: vectorized fused epilogue (float4 x2 per thread) -
__global__ __launch_bounds__(256) void epilogue_kernel(
    const float* __restrict__ x,
    const float* __restrict__ bmv, const float* __restrict__ bnv,
    float* __restrict__ out,
    const float* __restrict__ pm, const float* __restrict__ pn,
    const float* __restrict__ psh)
{
    int tid = threadIdx.x;
    int bid = blockIdx.x;
    int b = bid >> 4;                          // 16 blocks per batch row
    int wpb = g_wp[b], shb = g_sh[b];

    float maskmul = sigmf_fast(*pm) * 0.3f;
    float noisemul = sigmf_fast(*pn) * 0.05f;
    float ss_ = sigmf(*psh);
    float smix = 1.0f - ss_;
    float wa = fminf(fmaxf(1.0f - smix - ss_, 0.1f), 0.8f);
    float wb = smix * 0.5f, wc = ss_ * 0.5f;
    float tot = wa + wb + wc;
    wa /= tot; wb /= tot; wc /= tot;
    uint2 kn = tf2x32(0u, 42u, 0u, 1u);

#pragma unroll
    for (int it = 0; it < 2; it++) {
        uint32_t e0 = (uint32_t)bid * 2048u + (uint32_t)it * 1024u + (uint32_t)tid * 4u;
        int col0 = (int)(e0 & 32767u);
        int l = col0 >> 6, f = col0 & 63;      // 4 cols share l; f..f+3 within block
        int idx;
        if (shb > 0)      idx = (l >= wpb) ? min(l + shb, LL - 1) : l;
        else if (shb < 0) idx = (l >= wpb + shb && l < LL + shb) ? (l - shb) : l;
        else              idx = l;
        float4 gm4 = *reinterpret_cast<const float4*>(&g_gm[e0]);
        float4 gn4 = *reinterpret_cast<const float4*>(&g_gn[e0]);
        float4 xv4 = *reinterpret_cast<const float4*>(&x[e0]);
        float4 fv4 = *reinterpret_cast<const float4*>(&g_freq[e0]);
        float4 wv4 = *reinterpret_cast<const float4*>(&x[(size_t)b * LF + (size_t)idx * FF + f]);
        float4 sc4 = *reinterpret_cast<const float4*>(&g_scale[b * FF + f]);
        float4 bm4 = *reinterpret_cast<const float4*>(&bmv[col0]);
        float4 bn4 = *reinterpret_cast<const float4*>(&bnv[col0]);
        float nv0 = tf_normal(kn, e0 + 0u);
        float nv1 = tf_normal(kn, e0 + 1u);
        float nv2 = tf_normal(kn, e0 + 2u);
        float nv3 = tf_normal(kn, e0 + 3u);
        float4 o;
        {
            float mask = 1.0f - (1.0f - sigmf_fast(gm4.x + bm4.x)) * maskmul;
            float nm = softplusf_fast(gn4.x + bn4.x);
            o.x = (xv4.x * mask * sc4.x + nv0 * nm * noisemul) * wa + fv4.x * wb + wv4.x * wc;
        }
        {
            float mask = 1.0f - (1.0f - sigmf_fast(gm4.y + bm4.y)) * maskmul;
            float nm = softplusf_fast(gn4.y + bn4.y);
            o.y = (xv4.y * mask * sc4.y + nv1 * nm * noisemul) * wa + fv4.y * wb + wv4.y * wc;
        }
        {
            float mask = 1.0f - (1.0f - sigmf_fast(gm4.z + bm4.z)) * maskmul;
            float nm = softplusf_fast(gn4.z + bn4.z);
            o.z = (xv4.z * mask * sc4.z + nv2 * nm * noisemul) * wa + fv4.z * wb + wv4.z * wc;
        }
        {
            float mask = 1.0f - (1.0f - sigmf_fast(gm4.w + bm4.w)) * maskmul;
            float nm = softplusf_fast(gn4.w + bn4.w);
            o.w = (xv4.w * mask * sc4.w + nv3 * nm * noisemul) * wa + fv4.w * wb + wv4.w * wc;
        }
        *reinterpret_cast<float4*>(&out[e0]) = o;
    }
}

// ---------------- launch ------------------------------------------------------
extern "C" void kernel_launch(void* const* d_in, const int* in_sizes, int n_in,
                              void* d_out, int out_size) {
    const float* x   = (const float*)d_in[0];
    const float* w1  = (const float*)d_in[2];
    const float* b1  = (const float*)d_in[3];
    const float* w2  = (const float*)d_in[4];
    const float* b2  = (const float*)d_in[5];
    const float* w3  = (const float*)d_in[6];
    const float* b3  = (const float*)d_in[7];
    const float* wm  = (const float*)d_in[8];
    const float* bm  = (const float*)d_in[9];
    const float* wn  = (const float*)d_in[10];
    const float* bn  = (const float*)d_in[11];
    const float* ws  = (const float*)d_in[12];
    const float* bs  = (const float*)d_in[13];
    const float* pm  = (const float*)d_in[14];
    const float* pn  = (const float*)d_in[15];
    const float* psh = (const float*)d_in[16];
    const float* psc = (const float*)d_in[17];
    float* out = (float*)d_out;

    cudaFuncSetAttribute(gemm_kernel, cudaFuncAttributeMaxDynamicSharedMemorySize, DYN_SMEM);

    fft_mlp<<<2305, 256>>>(x, w1, b1, w2, b2, w3, b3, ws, bs, psh, psc);
    gemm_kernel<<<512, 512, DYN_SMEM>>>(wm, wn);
    epilogue_kernel<<<4096, 256>>>(x, bm, bn, out, pm, pn, psh);
}